// round 1
// baseline (speedup 1.0000x reference)
#include <cuda_runtime.h>

#define NNODES 100000
#define NEDGES 1600000
#define NB_SCAN ((NNODES + 1023) / 1024)

// ---- device scratch (no allocations allowed) ----
__device__ int   g_cnt[NNODES];
__device__ int   g_fill[NNODES];
__device__ int   g_rowptr[NNODES + 1];
__device__ int   g_csr[NEDGES];
__device__ float g_inv[NNODES];
__device__ float g_h0[NNODES * 64];
__device__ float g_h1[NNODES * 64];
__device__ int   g_bsum[NB_SCAN];
__device__ int   g_boff[NB_SCAN];

// ---------------- CSR build ----------------
__global__ void k_zero() {
    int i = blockIdx.x * blockDim.x + threadIdx.x;
    if (i < NNODES) { g_cnt[i] = 0; g_fill[i] = 0; }
    if (i == 0) g_rowptr[0] = 0;
}

__global__ void k_count(const int* __restrict__ ei) {
    int e = blockIdx.x * blockDim.x + threadIdx.x;
    if (e < NEDGES) atomicAdd(&g_cnt[ei[NEDGES + e]], 1);
}

__global__ void k_scan1() {
    __shared__ int s[1024];
    int t = threadIdx.x;
    int i = blockIdx.x * 1024 + t;
    s[t] = (i < NNODES) ? g_cnt[i] : 0;
    __syncthreads();
    for (int off = 1; off < 1024; off <<= 1) {
        int x = (t >= off) ? s[t - off] : 0;
        __syncthreads();
        s[t] += x;
        __syncthreads();
    }
    if (i < NNODES) g_rowptr[i + 1] = s[t];   // inclusive within block
    if (t == 1023) g_bsum[blockIdx.x] = s[t];
}

__global__ void k_scan2() {
    int run = 0;
    for (int b = 0; b < NB_SCAN; b++) { g_boff[b] = run; run += g_bsum[b]; }
}

__global__ void k_scan3() {
    int i = blockIdx.x * blockDim.x + threadIdx.x;
    if (i < NNODES) {
        g_rowptr[i + 1] += g_boff[i >> 10];
        int c = g_cnt[i];
        g_inv[i] = (c > 0) ? (1.0f / (float)c) : 0.0f;
    }
}

__global__ void k_scatter(const int* __restrict__ ei) {
    int e = blockIdx.x * blockDim.x + threadIdx.x;
    if (e < NEDGES) {
        int d = ei[NEDGES + e];
        int pos = g_rowptr[d] + atomicAdd(&g_fill[d], 1);
        g_csr[pos] = ei[e];
    }
}

// ---------------- fused SAGE layer: agg(mean) @ Wn + bn + h @ Wr (+relu) ----------------
// one warp per node; weights + per-warp row staging in SMEM
template<int DIN, bool RELU>
__global__ void __launch_bounds__(256) k_sage(const float* __restrict__ hin,
                                              float* __restrict__ hout,
                                              const float* __restrict__ Wn,
                                              const float* __restrict__ bn,
                                              const float* __restrict__ Wr) {
    __shared__ float  sWn[DIN * 64];
    __shared__ float  sWr[DIN * 64];
    __shared__ float  sbn[64];
    __shared__ float2 sagg[8][DIN / 2];
    __shared__ float2 sown[8][DIN / 2];

    int t = threadIdx.x;
    {
        const float4* w4n = (const float4*)Wn;
        const float4* w4r = (const float4*)Wr;
        float4* s4n = (float4*)sWn;
        float4* s4r = (float4*)sWr;
        #pragma unroll
        for (int i = t; i < DIN * 16; i += 256) { s4n[i] = w4n[i]; s4r[i] = w4r[i]; }
        if (t < 64) sbn[t] = bn[t];
    }
    __syncthreads();

    int w = t >> 5, lane = t & 31;
    int v = blockIdx.x * 8 + w;
    if (v >= NNODES) return;

    int r0 = g_rowptr[v], r1 = g_rowptr[v + 1];
    float invv = g_inv[v];

    if (DIN == 64) {
        const float2* h2 = (const float2*)hin;
        float2 acc = make_float2(0.f, 0.f);
        int i = r0;
        for (; i + 4 <= r1; i += 4) {
            int s0 = g_csr[i], s1 = g_csr[i + 1], s2 = g_csr[i + 2], s3 = g_csr[i + 3];
            float2 a = __ldg(&h2[s0 * 32 + lane]);
            float2 b = __ldg(&h2[s1 * 32 + lane]);
            float2 c = __ldg(&h2[s2 * 32 + lane]);
            float2 d = __ldg(&h2[s3 * 32 + lane]);
            acc.x += (a.x + b.x) + (c.x + d.x);
            acc.y += (a.y + b.y) + (c.y + d.y);
        }
        for (; i < r1; i++) {
            float2 a = __ldg(&h2[g_csr[i] * 32 + lane]);
            acc.x += a.x; acc.y += a.y;
        }
        acc.x *= invv; acc.y *= invv;
        float2 own = __ldg(&h2[v * 32 + lane]);
        sagg[w][lane] = acc;
        sown[w][lane] = own;
        __syncwarp();

        const float* sa = (const float*)&sagg[w][0];
        const float* so = (const float*)&sown[w][0];
        float2 o = make_float2(sbn[2 * lane], sbn[2 * lane + 1]);
        #pragma unroll
        for (int k = 0; k < 64; k++) {
            float a  = sa[k];
            float hk = so[k];
            float2 wn = *(const float2*)&sWn[k * 64 + 2 * lane];
            float2 wr = *(const float2*)&sWr[k * 64 + 2 * lane];
            o.x += a * wn.x + hk * wr.x;
            o.y += a * wn.y + hk * wr.y;
        }
        if (RELU) { o.x = fmaxf(o.x, 0.f); o.y = fmaxf(o.y, 0.f); }
        ((float2*)hout)[v * 32 + lane] = o;
    } else {
        // DIN == 32: one float per lane covers the row
        float acc = 0.f;
        int i = r0;
        for (; i + 4 <= r1; i += 4) {
            int s0 = g_csr[i], s1 = g_csr[i + 1], s2 = g_csr[i + 2], s3 = g_csr[i + 3];
            acc += __ldg(&hin[s0 * 32 + lane]) + __ldg(&hin[s1 * 32 + lane])
                 + __ldg(&hin[s2 * 32 + lane]) + __ldg(&hin[s3 * 32 + lane]);
        }
        for (; i < r1; i++) acc += __ldg(&hin[g_csr[i] * 32 + lane]);
        acc *= invv;
        float own = __ldg(&hin[v * 32 + lane]);
        ((float*)&sagg[w][0])[lane] = acc;
        ((float*)&sown[w][0])[lane] = own;
        __syncwarp();

        const float* sa = (const float*)&sagg[w][0];
        const float* so = (const float*)&sown[w][0];
        float2 o = make_float2(sbn[2 * lane], sbn[2 * lane + 1]);
        #pragma unroll
        for (int k = 0; k < 32; k++) {
            float a  = sa[k];
            float hk = so[k];
            float2 wn = *(const float2*)&sWn[k * 64 + 2 * lane];
            float2 wr = *(const float2*)&sWr[k * 64 + 2 * lane];
            o.x += a * wn.x + hk * wr.x;
            o.y += a * wn.y + hk * wr.y;
        }
        if (RELU) { o.x = fmaxf(o.x, 0.f); o.y = fmaxf(o.y, 0.f); }
        ((float2*)hout)[v * 32 + lane] = o;
    }
}

// ---------------- predictor: sigmoid(relu(h@Wp1+bp1)@Wp2+bp2) ----------------
__global__ void __launch_bounds__(256) k_pred(const float* __restrict__ hin,
                                              float* __restrict__ out,
                                              const float* __restrict__ Wp1,
                                              const float* __restrict__ bp1,
                                              const float* __restrict__ Wp2,
                                              const float* __restrict__ bp2) {
    __shared__ float  sW[64 * 64];
    __shared__ float  sb[64];
    __shared__ float  sw2[64];
    __shared__ float2 sown[8][32];

    int t = threadIdx.x;
    {
        const float4* w4 = (const float4*)Wp1;
        float4* s4 = (float4*)sW;
        #pragma unroll
        for (int i = t; i < 1024; i += 256) s4[i] = w4[i];
        if (t < 64) { sb[t] = bp1[t]; sw2[t] = Wp2[t]; }
    }
    __syncthreads();

    int w = t >> 5, lane = t & 31;
    int v = blockIdx.x * 8 + w;
    if (v >= NNODES) return;

    const float2* h2 = (const float2*)hin;
    sown[w][lane] = __ldg(&h2[v * 32 + lane]);
    __syncwarp();

    const float* so = (const float*)&sown[w][0];
    float2 p = make_float2(sb[2 * lane], sb[2 * lane + 1]);
    #pragma unroll
    for (int k = 0; k < 64; k++) {
        float hk = so[k];
        float2 wn = *(const float2*)&sW[k * 64 + 2 * lane];
        p.x += hk * wn.x;
        p.y += hk * wn.y;
    }
    p.x = fmaxf(p.x, 0.f);
    p.y = fmaxf(p.y, 0.f);
    float val = p.x * sw2[2 * lane] + p.y * sw2[2 * lane + 1];
    #pragma unroll
    for (int off = 16; off; off >>= 1) val += __shfl_xor_sync(0xffffffffu, val, off);
    if (lane == 0) {
        float b2 = __ldg(bp2);
        out[v] = 1.0f / (1.0f + __expf(-(val + b2)));
    }
}

// ---------------- launch ----------------
extern "C" void kernel_launch(void* const* d_in, const int* in_sizes, int n_in,
                              void* d_out, int out_size) {
    const float* x   = (const float*)d_in[0];
    const int*   ei  = (const int*)d_in[1];
    const float* Wn0 = (const float*)d_in[2];
    const float* bn0 = (const float*)d_in[3];
    const float* Wr0 = (const float*)d_in[4];
    const float* Wn1 = (const float*)d_in[5];
    const float* bn1 = (const float*)d_in[6];
    const float* Wr1 = (const float*)d_in[7];
    const float* Wn2 = (const float*)d_in[8];
    const float* bn2 = (const float*)d_in[9];
    const float* Wr2 = (const float*)d_in[10];
    const float* Wp1 = (const float*)d_in[11];
    const float* bp1 = (const float*)d_in[12];
    const float* Wp2 = (const float*)d_in[13];
    const float* bp2 = (const float*)d_in[14];
    float* out = (float*)d_out;

    float *h0 = 0, *h1 = 0;
    cudaGetSymbolAddress((void**)&h0, g_h0);
    cudaGetSymbolAddress((void**)&h1, g_h1);

    int nb_nodes = (NNODES + 255) / 256;
    int nb_edges = (NEDGES + 255) / 256;
    int nb_warp  = (NNODES + 7) / 8;

    // CSR build
    k_zero   <<<nb_nodes, 256>>>();
    k_count  <<<nb_edges, 256>>>(ei);
    k_scan1  <<<NB_SCAN, 1024>>>();
    k_scan2  <<<1, 1>>>();
    k_scan3  <<<nb_nodes, 256>>>();
    k_scatter<<<nb_edges, 256>>>(ei);

    // GNN
    k_sage<32, true ><<<nb_warp, 256>>>(x,  h0, Wn0, bn0, Wr0);
    k_sage<64, true ><<<nb_warp, 256>>>(h0, h1, Wn1, bn1, Wr1);
    k_sage<64, false><<<nb_warp, 256>>>(h1, h0, Wn2, bn2, Wr2);
    k_pred<<<nb_warp, 256>>>(h0, out, Wp1, bp1, Wp2, bp2);
}

// round 3
// speedup vs baseline: 1.1143x; 1.1143x over previous
#include <cuda_runtime.h>

#define NNODES 100000
#define NEDGES 1600000
#define NB_SCAN ((NNODES + 1023) / 1024)
#define NPB 64            // nodes per block in sage kernels
#define THREADS 256

// ---- device scratch (no allocations allowed) ----
__device__ int   g_cnt[NNODES];
__device__ int   g_fill[NNODES];
__device__ int   g_rowptr[NNODES + 1];
__device__ int   g_csr[NEDGES];
__device__ float g_inv[NNODES];
__device__ float g_h0[NNODES * 64];
__device__ float g_h1[NNODES * 64];
__device__ int   g_bsum[NB_SCAN];
__device__ int   g_boff[NB_SCAN];

union U64 { unsigned long long u; float2 f; };

__device__ __forceinline__ void FMA2(unsigned long long& d,
                                     unsigned long long a,
                                     unsigned long long b) {
    asm("fma.rn.f32x2 %0, %1, %2, %0;" : "+l"(d) : "l"(a), "l"(b));
}

// ---------------- CSR build ----------------
__global__ void k_zero() {
    int i = blockIdx.x * blockDim.x + threadIdx.x;
    if (i < NNODES) { g_cnt[i] = 0; g_fill[i] = 0; }
    if (i == 0) g_rowptr[0] = 0;
}

__global__ void k_count(const int* __restrict__ ei) {
    int e = blockIdx.x * blockDim.x + threadIdx.x;
    if (e < NEDGES) atomicAdd(&g_cnt[ei[NEDGES + e]], 1);
}

__global__ void k_scan1() {
    __shared__ int s[1024];
    int t = threadIdx.x;
    int i = blockIdx.x * 1024 + t;
    s[t] = (i < NNODES) ? g_cnt[i] : 0;
    __syncthreads();
    for (int off = 1; off < 1024; off <<= 1) {
        int x = (t >= off) ? s[t - off] : 0;
        __syncthreads();
        s[t] += x;
        __syncthreads();
    }
    if (i < NNODES) g_rowptr[i + 1] = s[t];   // inclusive within block
    if (t == 1023) g_bsum[blockIdx.x] = s[t];
}

__global__ void k_scan2() {   // parallel scan over block sums (98 entries)
    __shared__ int s[128];
    int t = threadIdx.x;
    int v = (t < NB_SCAN) ? g_bsum[t] : 0;
    s[t] = v;
    __syncthreads();
    for (int off = 1; off < 128; off <<= 1) {
        int x = (t >= off) ? s[t - off] : 0;
        __syncthreads();
        s[t] += x;
        __syncthreads();
    }
    if (t < NB_SCAN) g_boff[t] = s[t] - v;    // exclusive
}

__global__ void k_scan3() {
    int i = blockIdx.x * blockDim.x + threadIdx.x;
    if (i < NNODES) {
        g_rowptr[i + 1] += g_boff[i >> 10];
        int c = g_cnt[i];
        g_inv[i] = (c > 0) ? (1.0f / (float)c) : 0.0f;
    }
}

__global__ void k_scatter(const int* __restrict__ ei) {
    int e = blockIdx.x * blockDim.x + threadIdx.x;
    if (e < NEDGES) {
        int d = ei[NEDGES + e];
        int pos = g_rowptr[d] + atomicAdd(&g_fill[d], 1);
        g_csr[pos] = ei[e];
    }
}

// ---------------- aggregation helpers ----------------
// DIN=64: warp aggregates node v, lane holds features {2*lane, 2*lane+1}
__device__ __forceinline__ void agg_store64(const float* __restrict__ hin,
                                            float* sAO, int v, int vloc, int lane) {
    int r0 = g_rowptr[v], r1 = g_rowptr[v + 1];
    float invv = g_inv[v];
    const float2* h2 = (const float2*)hin;
    float2 acc = make_float2(0.f, 0.f);
    int i = r0;
    for (; i + 4 <= r1; i += 4) {
        int s0 = g_csr[i], s1 = g_csr[i + 1], s2 = g_csr[i + 2], s3 = g_csr[i + 3];
        float2 a = __ldg(&h2[s0 * 32 + lane]);
        float2 b = __ldg(&h2[s1 * 32 + lane]);
        float2 c = __ldg(&h2[s2 * 32 + lane]);
        float2 d = __ldg(&h2[s3 * 32 + lane]);
        acc.x += (a.x + b.x) + (c.x + d.x);
        acc.y += (a.y + b.y) + (c.y + d.y);
    }
    for (; i < r1; i++) {
        float2 a = __ldg(&h2[g_csr[i] * 32 + lane]);
        acc.x += a.x; acc.y += a.y;
    }
    float2 own = __ldg(&h2[v * 32 + lane]);
    *(float2*)&sAO[(2 * lane) * 132 + 2 * vloc]     = make_float2(acc.x * invv, own.x);
    *(float2*)&sAO[(2 * lane + 1) * 132 + 2 * vloc] = make_float2(acc.y * invv, own.y);
}

// DIN=32: lane holds feature {lane}
__device__ __forceinline__ void agg_store32(const float* __restrict__ hin,
                                            float* sAO, int v, int vloc, int lane) {
    int r0 = g_rowptr[v], r1 = g_rowptr[v + 1];
    float invv = g_inv[v];
    float acc = 0.f;
    int i = r0;
    for (; i + 4 <= r1; i += 4) {
        int s0 = g_csr[i], s1 = g_csr[i + 1], s2 = g_csr[i + 2], s3 = g_csr[i + 3];
        acc += __ldg(&hin[s0 * 32 + lane]) + __ldg(&hin[s1 * 32 + lane])
             + __ldg(&hin[s2 * 32 + lane]) + __ldg(&hin[s3 * 32 + lane]);
    }
    for (; i < r1; i++) acc += __ldg(&hin[g_csr[i] * 32 + lane]);
    float own = __ldg(&hin[v * 32 + lane]);
    *(float2*)&sAO[lane * 132 + 2 * vloc] = make_float2(acc * invv, own);
}

// ---------------- fused SAGE layer ----------------
// smem: sW[DIN][64][2] ({Wn,Wr} interleaved), sAO[DIN][132] ({agg,own} interleaved,
// 2 slots per node), sb[192]
template<int DIN, bool RELU>
__global__ void __launch_bounds__(THREADS) k_sage(const float* __restrict__ hin,
                                                  float* __restrict__ hout,
                                                  const float* __restrict__ Wn,
                                                  const float* __restrict__ bn,
                                                  const float* __restrict__ Wr) {
    extern __shared__ float smem[];
    float* sW  = smem;                     // DIN*128
    float* sAO = smem + DIN * 128;         // DIN*132
    float* sb  = sAO + DIN * 132;          // 192

    int t = threadIdx.x;
    for (int i = t; i < DIN * 64; i += THREADS) {
        int k = i >> 6, c = i & 63;
        sW[(k << 7) + 2 * c]     = Wn[i];
        sW[(k << 7) + 2 * c + 1] = Wr[i];
    }
    if (t < 64) sb[t] = bn[t];

    int w = t >> 5, lane = t & 31;
    int vbase = blockIdx.x * NPB;
    __syncthreads();

    // aggregation: warp w -> 8 nodes
    for (int j = 0; j < 8; j++) {
        int vloc = w * 8 + j;
        int v = vbase + vloc;
        if (v < NNODES) {
            if (DIN == 64) agg_store64(hin, sAO, v, vloc, lane);
            else           agg_store32(hin, sAO, v, vloc, lane);
        }
    }
    __syncthreads();

    // GEMM: thread -> 4 nodes x 4 cols, f32x2: {a,h} . {wn,wr}
    int cg = t & 15, ng = t >> 4;
    unsigned long long acc[4][4];
    #pragma unroll
    for (int j = 0; j < 4; j++)
        #pragma unroll
        for (int c = 0; c < 4; c++) acc[j][c] = 0ull;

    #pragma unroll 8
    for (int k = 0; k < DIN; k++) {
        const float* wrow = &sW[(k << 7) + (cg << 3)];
        ulonglong2 w0 = *(const ulonglong2*)wrow;
        ulonglong2 w1 = *(const ulonglong2*)(wrow + 4);
        const float* arow = &sAO[k * 132 + (ng << 3)];
        ulonglong2 a0 = *(const ulonglong2*)arow;
        ulonglong2 a1 = *(const ulonglong2*)(arow + 4);
        unsigned long long ahv[4] = {a0.x, a0.y, a1.x, a1.y};
        unsigned long long wv[4]  = {w0.x, w0.y, w1.x, w1.y};
        #pragma unroll
        for (int j = 0; j < 4; j++)
            #pragma unroll
            for (int c = 0; c < 4; c++) FMA2(acc[j][c], ahv[j], wv[c]);
    }

    #pragma unroll
    for (int j = 0; j < 4; j++) {
        int v = vbase + 4 * ng + j;
        if (v < NNODES) {
            float4 o;
            float r[4];
            #pragma unroll
            for (int c = 0; c < 4; c++) {
                U64 u; u.u = acc[j][c];
                float val = u.f.x + u.f.y + sb[4 * cg + c];
                r[c] = RELU ? fmaxf(val, 0.f) : val;
            }
            o.x = r[0]; o.y = r[1]; o.z = r[2]; o.w = r[3];
            ((float4*)hout)[v * 16 + cg] = o;
        }
    }
}

// ---------------- layer 2 + predictor fused (DIN=64, no relu) ----------------
__global__ void __launch_bounds__(THREADS) k_sage_pred(const float* __restrict__ hin,
                                                       float* __restrict__ out,
                                                       const float* __restrict__ Wn,
                                                       const float* __restrict__ bn,
                                                       const float* __restrict__ Wr,
                                                       const float* __restrict__ Wp1,
                                                       const float* __restrict__ bp1,
                                                       const float* __restrict__ Wp2,
                                                       const float* __restrict__ bp2) {
    extern __shared__ float smem[];
    float* sW  = smem;                 // 64*128
    float* sAO = smem + 64 * 128;      // 64*132
    float* sb  = sAO + 64 * 132;       // 192

    int t = threadIdx.x;
    for (int i = t; i < 4096; i += THREADS) {
        int k = i >> 6, c = i & 63;
        sW[(k << 7) + 2 * c]     = Wn[i];
        sW[(k << 7) + 2 * c + 1] = Wr[i];
    }
    if (t < 64) sb[t] = bn[t];
    float bp2v = __ldg(bp2);

    int w = t >> 5, lane = t & 31;
    int vbase = blockIdx.x * NPB;
    __syncthreads();

    for (int j = 0; j < 8; j++) {
        int vloc = w * 8 + j;
        int v = vbase + vloc;
        if (v < NNODES) agg_store64(hin, sAO, v, vloc, lane);
    }
    __syncthreads();

    int cg = t & 15, ng = t >> 4;
    unsigned long long acc[4][4];
    #pragma unroll
    for (int j = 0; j < 4; j++)
        #pragma unroll
        for (int c = 0; c < 4; c++) acc[j][c] = 0ull;

    #pragma unroll 8
    for (int k = 0; k < 64; k++) {
        const float* wrow = &sW[(k << 7) + (cg << 3)];
        ulonglong2 w0 = *(const ulonglong2*)wrow;
        ulonglong2 w1 = *(const ulonglong2*)(wrow + 4);
        const float* arow = &sAO[k * 132 + (ng << 3)];
        ulonglong2 a0 = *(const ulonglong2*)arow;
        ulonglong2 a1 = *(const ulonglong2*)(arow + 4);
        unsigned long long ahv[4] = {a0.x, a0.y, a1.x, a1.y};
        unsigned long long wv[4]  = {w0.x, w0.y, w1.x, w1.y};
        #pragma unroll
        for (int j = 0; j < 4; j++)
            #pragma unroll
            for (int c = 0; c < 4; c++) FMA2(acc[j][c], ahv[j], wv[c]);
    }

    // finalize h (no relu), stage into sH (reuse sAO region)
    float hv[4][4];
    #pragma unroll
    for (int j = 0; j < 4; j++)
        #pragma unroll
        for (int c = 0; c < 4; c++) {
            U64 u; u.u = acc[j][c];
            hv[j][c] = u.f.x + u.f.y + sb[4 * cg + c];
        }
    __syncthreads();                 // all reads of sAO/sW/sb done
    float* sH = sAO;                 // [64 nodes][64 cols]
    #pragma unroll
    for (int j = 0; j < 4; j++) {
        float4 o; o.x = hv[j][0]; o.y = hv[j][1]; o.z = hv[j][2]; o.w = hv[j][3];
        *(float4*)&sH[(4 * ng + j) * 64 + 4 * cg] = o;
    }
    // reload weights for predictor
    for (int i = t; i < 4096; i += THREADS) sW[i] = Wp1[i];
    if (t < 64) { sb[t] = bp1[t]; sb[64 + t] = Wp2[t]; }
    __syncthreads();

    float pa[4][4];
    #pragma unroll
    for (int j = 0; j < 4; j++)
        #pragma unroll
        for (int c = 0; c < 4; c++) pa[j][c] = sb[4 * cg + c];

    #pragma unroll 8
    for (int k = 0; k < 64; k++) {
        float4 wv = *(const float4*)&sW[k * 64 + 4 * cg];
        float h0v = sH[(4 * ng + 0) * 64 + k];
        float h1v = sH[(4 * ng + 1) * 64 + k];
        float h2v = sH[(4 * ng + 2) * 64 + k];
        float h3v = sH[(4 * ng + 3) * 64 + k];
        pa[0][0] += h0v * wv.x; pa[0][1] += h0v * wv.y; pa[0][2] += h0v * wv.z; pa[0][3] += h0v * wv.w;
        pa[1][0] += h1v * wv.x; pa[1][1] += h1v * wv.y; pa[1][2] += h1v * wv.z; pa[1][3] += h1v * wv.w;
        pa[2][0] += h2v * wv.x; pa[2][1] += h2v * wv.y; pa[2][2] += h2v * wv.z; pa[2][3] += h2v * wv.w;
        pa[3][0] += h3v * wv.x; pa[3][1] += h3v * wv.y; pa[3][2] += h3v * wv.z; pa[3][3] += h3v * wv.w;
    }

    float4 w2 = *(const float4*)&sb[64 + 4 * cg];
    #pragma unroll
    for (int j = 0; j < 4; j++) {
        float val = fmaxf(pa[j][0], 0.f) * w2.x + fmaxf(pa[j][1], 0.f) * w2.y
                  + fmaxf(pa[j][2], 0.f) * w2.z + fmaxf(pa[j][3], 0.f) * w2.w;
        #pragma unroll
        for (int off = 1; off < 16; off <<= 1)
            val += __shfl_xor_sync(0xffffffffu, val, off);
        if (cg == 0) {
            int v = vbase + 4 * ng + j;
            if (v < NNODES) out[v] = 1.0f / (1.0f + __expf(-(val + bp2v)));
        }
    }
}

// ---------------- launch ----------------
extern "C" void kernel_launch(void* const* d_in, const int* in_sizes, int n_in,
                              void* d_out, int out_size) {
    const float* x   = (const float*)d_in[0];
    const int*   ei  = (const int*)d_in[1];
    const float* Wn0 = (const float*)d_in[2];
    const float* bn0 = (const float*)d_in[3];
    const float* Wr0 = (const float*)d_in[4];
    const float* Wn1 = (const float*)d_in[5];
    const float* bn1 = (const float*)d_in[6];
    const float* Wr1 = (const float*)d_in[7];
    const float* Wn2 = (const float*)d_in[8];
    const float* bn2 = (const float*)d_in[9];
    const float* Wr2 = (const float*)d_in[10];
    const float* Wp1 = (const float*)d_in[11];
    const float* bp1 = (const float*)d_in[12];
    const float* Wp2 = (const float*)d_in[13];
    const float* bp2 = (const float*)d_in[14];
    float* out = (float*)d_out;

    float *h0 = 0, *h1 = 0;
    cudaGetSymbolAddress((void**)&h0, g_h0);
    cudaGetSymbolAddress((void**)&h1, g_h1);

    const int smem32 = (32 * 128 + 32 * 132 + 192) * 4;   // 34048
    const int smem64 = (64 * 128 + 64 * 132 + 192) * 4;   // 67328
    cudaFuncSetAttribute(k_sage<64, true>,  cudaFuncAttributeMaxDynamicSharedMemorySize, smem64);
    cudaFuncSetAttribute(k_sage_pred,       cudaFuncAttributeMaxDynamicSharedMemorySize, smem64);

    int nb_nodes = (NNODES + 255) / 256;
    int nb_edges = (NEDGES + 255) / 256;
    int nb_tile  = (NNODES + NPB - 1) / NPB;

    // CSR build
    k_zero   <<<nb_nodes, 256>>>();
    k_count  <<<nb_edges, 256>>>(ei);
    k_scan1  <<<NB_SCAN, 1024>>>();
    k_scan2  <<<1, 128>>>();
    k_scan3  <<<nb_nodes, 256>>>();
    k_scatter<<<nb_edges, 256>>>(ei);

    // GNN
    k_sage<32, true ><<<nb_tile, THREADS, smem32>>>(x,  h0, Wn0, bn0, Wr0);
    k_sage<64, true ><<<nb_tile, THREADS, smem64>>>(h0, h1, Wn1, bn1, Wr1);
    k_sage_pred      <<<nb_tile, THREADS, smem64>>>(h1, out, Wn2, bn2, Wr2,
                                                    Wp1, bp1, Wp2, bp2);
}